// round 16
// baseline (speedup 1.0000x reference)
#include <cuda_runtime.h>
#include <cuda_bf16.h>
#include <cstdint>

// Problem constants (match reference)
#define NN 50000
#define EE 600000
#define GG 64
#define HH 128
#define CC 10

#define SCAN_T 256
#define SCAN_NB ((NN + SCAN_T - 1) / SCAN_T)   // 196

typedef unsigned long long u64;
typedef unsigned int u32;
typedef unsigned short u16;

// ---------------- scratch (static device globals; no runtime alloc) ----------------
// Zeroed-per-launch region: one contiguous memset.
struct ZReg {
    int   deg[NN];
    int   bstat[SCAN_NB];          // lookback status: 0=none,1=agg ready,2=prefix ready
    float sums[GG * HH];
    float cnt[GG];
};
__device__ ZReg g_z;
#define g_deg   g_z.deg
#define g_bstat g_z.bstat
#define g_sums  g_z.sums
#define g_cnt   g_z.cnt

__device__ int   g_off[NN];        // CSR offsets (fill bumps to end)
__device__ float g_dinv[NN];       // rsqrt(deg+1)
__device__ int   g_bagg[SCAN_NB];  // per-block degree totals (published)
__device__ int   g_bpre[SCAN_NB];  // inclusive prefixes (published)
__device__ int2  g_csr[EE];        // {src, bits(dinv[src])} grouped by dst
__device__ uint4 g_xbf[NN * 16];   // x in bf16 (row = 16 uint4 = 128 bf16)
__device__ uint4 g_hbf[NN * 16];   // h = relu(Agg(x)@W1+b1) in bf16
// Precomputed W1 split planes, pre-padded [n][136] bf16; hi plane then lo plane.
#define AST 136   // padded row stride in bf16
#define ASTW 68   // in 32-bit words
#define PLANE_U16 (128 * AST)              // 17408 u16 per plane
__device__ uint4 g_W1p[(PLANE_U16 * 2) / 8];   // 4352 uint4 = 69632 B

// ---------------- bf16 helpers ----------------
__device__ __forceinline__ float4 bf2f4(u32 a, u32 b) {
    __nv_bfloat162 p0 = *(__nv_bfloat162*)&a;
    __nv_bfloat162 p1 = *(__nv_bfloat162*)&b;
    float2 f0 = __bfloat1622float2(p0);
    float2 f1 = __bfloat1622float2(p1);
    return make_float4(f0.x, f0.y, f1.x, f1.y);
}
__device__ __forceinline__ u32 f2bf2(float a, float b) {
    __nv_bfloat162 p = __float22bfloat162_rn(make_float2(a, b));
    return *(u32*)&p;
}

// ---------------- warp-level bf16 MMA (sm_80+ PTX, legal on compute_103) -------
__device__ __forceinline__ void mma16816(float* d, u32 a0, u32 a1, u32 a2, u32 a3,
                                         u32 b0, u32 b1) {
    asm volatile(
        "mma.sync.aligned.m16n8k16.row.col.f32.bf16.bf16.f32 "
        "{%0,%1,%2,%3}, {%4,%5,%6,%7}, {%8,%9}, {%0,%1,%2,%3};"
        : "+f"(d[0]), "+f"(d[1]), "+f"(d[2]), "+f"(d[3])
        : "r"(a0), "r"(a1), "r"(a2), "r"(a3), "r"(b0), "r"(b1));
}

// ---------------- inline dtype detect (no kernel, no global flag) --------------
// int64 indices are < NN < 2^32, so OR of sampled 64-bit words stays < 2^32.
// int32 data fused pairwise puts the NEXT index in the high half: any nonzero
// odd-position value makes a word >= 2^32. 8 samples -> misdetect P ~ (2e-5)^8.
__device__ __forceinline__ int detect64(const void* ei) {
    const long long* p = (const long long*)ei;
    long long m = p[1] | p[3] | p[5] | p[7] | p[9] | p[11] | p[13] | p[15];
    return ((u64)m) < (1ULL << 32);
}

// ---------------- index load helper (dtype-agnostic) ----------------
__device__ __forceinline__ int load_idx(const void* p, long long i, int is64) {
    if (is64) return (int)(((const long long*)p)[i]);
    return ((const int*)p)[i];
}

// ---------------- K1: x->bf16, in-degrees, W1 split planes ----------------
__global__ void prep_kernel(const float* __restrict__ x, const void* __restrict__ ei,
                            const float* __restrict__ W1) {
    int i = blockIdx.x * blockDim.x + threadIdx.x;
    if (i < NN * 16) {
        float4 va = ((const float4*)x)[i * 2];
        float4 vb = ((const float4*)x)[i * 2 + 1];
        uint4 o;
        o.x = f2bf2(va.x, va.y);
        o.y = f2bf2(va.z, va.w);
        o.z = f2bf2(vb.x, vb.y);
        o.w = f2bf2(vb.z, vb.w);
        g_xbf[i] = o;
    }
    if (i < EE) {
        int is64 = detect64(ei);
        int dst = load_idx(ei, (long long)EE + i, is64);
        dst = min(max(dst, 0), NN - 1);
        atomicAdd(&g_deg[dst], 1);
    }
    if (i < 128 * 128) {
        int k = i >> 7, n = i & 127;
        float w = W1[i];
        __nv_bfloat16 hi = __float2bfloat16_rn(w);
        __nv_bfloat16 lo = __float2bfloat16_rn(w - __bfloat162float(hi));
        u16* planes = (u16*)g_W1p;
        planes[n * AST + k]             = *(u16*)&hi;
        planes[PLANE_U16 + n * AST + k] = *(u16*)&lo;
    }
}

// ---------------- K2: single-pass scan (decoupled lookback) + dinv + offsets --
__global__ void __launch_bounds__(SCAN_T) scan_kernel() {
    __shared__ int ws[8];
    __shared__ int sh_base;
    int b = blockIdx.x, t = threadIdx.x;
    int i = b * SCAN_T + t;
    int v = (i < NN) ? g_deg[i] : 0;
    if (i < NN) g_dinv[i] = rsqrtf((float)(v + 1));

    // block-local inclusive scan (shfl)
    int lane = t & 31, w = t >> 5;
    int s = v;
    #pragma unroll
    for (int o = 1; o < 32; o <<= 1) {
        int u = __shfl_up_sync(0xffffffffu, s, o);
        if (lane >= o) s += u;
    }
    if (lane == 31) ws[w] = s;
    __syncthreads();
    if (w == 0 && lane < 8) {
        int x2 = ws[lane];
        #pragma unroll
        for (int o = 1; o < 8; o <<= 1) {
            int u = __shfl_up_sync(0xffu, x2, o, 8);
            if (lane >= o) x2 += u;
        }
        ws[lane] = x2;
    }
    __syncthreads();
    if (w > 0) s += ws[w - 1];                  // inclusive within block

    // publish aggregate (block total = s at t=255 since padding v=0)
    if (t == SCAN_T - 1) {
        if (b == 0) {
            atomicExch(&g_bpre[0], s);
            __threadfence();
            atomicExch(&g_bstat[0], 2);
        } else {
            atomicExch(&g_bagg[b], s);
            __threadfence();
            atomicExch(&g_bstat[b], 1);
        }
    }

    // lookback (thread 0)
    if (t == 0) {
        int base = 0;
        if (b > 0) {
            int j = b - 1;
            while (true) {
                int st;
                do { st = atomicAdd(&g_bstat[j], 0); } while (st == 0);
                __threadfence();
                if (st == 2) { base += atomicAdd(&g_bpre[j], 0); break; }
                base += atomicAdd(&g_bagg[j], 0);
                j--;
            }
        }
        sh_base = base;
    }
    __syncthreads();
    int base = sh_base;

    // publish inclusive prefix for successors
    if (t == SCAN_T - 1 && b > 0) {
        atomicExch(&g_bpre[b], base + s);
        __threadfence();
        atomicExch(&g_bstat[b], 2);
    }

    if (i < NN) g_off[i] = base + s - v;        // exclusive offset
}

// ---------------- K3: scatter edges into dst-grouped CSR (bumps g_off) --------
__global__ void fill_kernel(const void* __restrict__ ei) {
    int e = blockIdx.x * blockDim.x + threadIdx.x;
    if (e < EE) {
        int is64 = detect64(ei);
        int src = load_idx(ei, e, is64);
        int dst = load_idx(ei, (long long)EE + e, is64);
        src = min(max(src, 0), NN - 1);
        dst = min(max(dst, 0), NN - 1);
        int pos = atomicAdd(&g_off[dst], 1);    // g_off[dst] ends at CSR end
        g_csr[pos] = make_int2(src, __float_as_int(g_dinv[src]));
    }
}

// ---------------- dual-row agg (predicated batch-4, no serial tail) -----------
// NOTE: after fill, g_off[dst] == END of dst's edge range; start = end - deg.
__device__ __forceinline__ void fma4(float4& a, float w, const float4& v) {
    a.x = fmaf(w, v.x, a.x); a.y = fmaf(w, v.y, a.y);
    a.z = fmaf(w, v.z, a.z); a.w = fmaf(w, v.w, a.w);
}

__device__ __forceinline__ void agg_row2_bf(const uint4* __restrict__ sf, int dst, int sub,
                                            float4& o0, float4& o1) {
    float di = g_dinv[dst];
    uint4 sv = sf[dst * 16 + sub];                 // self loop
    float4 a0 = bf2f4(sv.x, sv.y);
    float4 a1 = bf2f4(sv.z, sv.w);
    a0.x *= di; a0.y *= di; a0.z *= di; a0.w *= di;
    a1.x *= di; a1.y *= di; a1.z *= di; a1.w *= di;
    float4 b0 = make_float4(0.f, 0.f, 0.f, 0.f);
    float4 b1 = make_float4(0.f, 0.f, 0.f, 0.f);

    int end = g_off[dst];
    int e0 = end - g_deg[dst];
    int last = end - 1;
    for (int b = e0; b < end; b += 4) {
        int i1 = b + 1, i2 = b + 2, i3 = b + 3;
        int2 c0 = g_csr[b];
        int2 c1 = g_csr[min(i1, last)];
        int2 c2 = g_csr[min(i2, last)];
        int2 c3 = g_csr[min(i3, last)];
        uint4 v0 = sf[c0.x * 16 + sub];
        uint4 v1 = sf[c1.x * 16 + sub];
        uint4 v2 = sf[c2.x * 16 + sub];
        uint4 v3 = sf[c3.x * 16 + sub];
        float w0 = __int_as_float(c0.y);
        float w1 = (i1 < end) ? __int_as_float(c1.y) : 0.f;
        float w2 = (i2 < end) ? __int_as_float(c2.y) : 0.f;
        float w3 = (i3 < end) ? __int_as_float(c3.y) : 0.f;
        fma4(a0, w0, bf2f4(v0.x, v0.y)); fma4(a1, w0, bf2f4(v0.z, v0.w));
        fma4(b0, w1, bf2f4(v1.x, v1.y)); fma4(b1, w1, bf2f4(v1.z, v1.w));
        fma4(a0, w2, bf2f4(v2.x, v2.y)); fma4(a1, w2, bf2f4(v2.z, v2.w));
        fma4(b0, w3, bf2f4(v3.x, v3.y)); fma4(b1, w3, bf2f4(v3.z, v3.w));
    }
    a0.x += b0.x; a0.y += b0.y; a0.z += b0.z; a0.w += b0.w;
    a1.x += b1.x; a1.y += b1.y; a1.z += b1.z; a1.w += b1.w;
    a0.x *= di; a0.y *= di; a0.z *= di; a0.w *= di;
    a1.x *= di; a1.y *= di; a1.z *= di; a1.w *= di;
    o0 = a0; o1 = a1;
}

// ---------------- K4: FUSED  h = relu(Agg(x) @ W1 + b1) via split-bf16 MMA ----
#define SM_BIAS 512
#define SM_A 1024
#define SM_BHI (1024 + 34816)
#define SM_BLO (1024 + 34816 + 34816)
#define FUSED_SMEM (1024 + 34816 + 34816 + 34816)

__global__ void __launch_bounds__(256, 2)
fused_agg_mma(const float* __restrict__ b1) {
    extern __shared__ char smc[];
    float* bias_s = (float*)(smc + SM_BIAS);
    u32* Aw  = (u32*)(smc + SM_A);
    u32* BwH = (u32*)(smc + SM_BHI);
    u32* BwL = (u32*)(smc + SM_BLO);
    int tid = threadIdx.x;
    int wid = tid >> 5, lane = tid & 31;
    int sub = lane & 15, half = lane >> 4;
    int row0 = blockIdx.x * 128;

    if (tid < 128) bias_s[tid] = b1[tid];

    // ---- B planes: straight uint4 copy of precomputed Whi/Wlo ----
    uint4* bdst = (uint4*)(smc + SM_BHI);
    #pragma unroll 4
    for (int i = tid; i < (PLANE_U16 * 2) / 8; i += 256)
        bdst[i] = g_W1p[i];

    // ---- A tile: aggregate 128 rows into As[m][k] bf16 (stride 136) ----
    const uint4* sfx = (const uint4*)g_xbf;
    #pragma unroll 1
    for (int r = 0; r < 8; r++) {
        int m = wid * 16 + r * 2 + half;
        int dst = row0 + m;
        float4 o0 = make_float4(0.f, 0.f, 0.f, 0.f);
        float4 o1 = make_float4(0.f, 0.f, 0.f, 0.f);
        if (dst < NN) agg_row2_bf(sfx, dst, sub, o0, o1);
        uint4 pk;
        pk.x = f2bf2(o0.x, o0.y); pk.y = f2bf2(o0.z, o0.w);
        pk.z = f2bf2(o1.x, o1.y); pk.w = f2bf2(o1.z, o1.w);
        *(uint4*)(smc + SM_A + m * (AST * 2) + sub * 16) = pk;
    }
    __syncthreads();

    // ---- MMA: each warp computes rows [wid*16, +16) x all 128 cols ----
    int g = lane >> 2, tc = lane & 3;
    int wrow = wid * 16;
    float acc[16][4];
    #pragma unroll
    for (int j = 0; j < 16; j++)
        #pragma unroll
        for (int q = 0; q < 4; q++) acc[j][q] = 0.f;

    #pragma unroll 1
    for (int ks = 0; ks < 8; ks++) {
        int k0w = ks * 8;                       // 16 bf16 = 8 words
        u32 a0 = Aw[(wrow + g) * ASTW + k0w + tc];
        u32 a1 = Aw[(wrow + g + 8) * ASTW + k0w + tc];
        u32 a2 = Aw[(wrow + g) * ASTW + k0w + tc + 4];
        u32 a3 = Aw[(wrow + g + 8) * ASTW + k0w + tc + 4];
        #pragma unroll
        for (int j = 0; j < 16; j++) {
            int bi = (j * 8 + g) * ASTW + k0w + tc;
            u32 bh0 = BwH[bi], bh1 = BwH[bi + 4];
            u32 bl0 = BwL[bi], bl1 = BwL[bi + 4];
            mma16816(acc[j], a0, a1, a2, a3, bh0, bh1);
            mma16816(acc[j], a0, a1, a2, a3, bl0, bl1);
        }
    }
    __syncthreads();     // done reading As/Bs; reuse As for output staging

    // ---- epilogue: bias + relu, pack bf16 into As, then coalesced store ----
    #pragma unroll
    for (int j = 0; j < 16; j++) {
        int c = j * 8 + tc * 2;
        float bv0 = bias_s[c], bv1 = bias_s[c + 1];
        u32 lo = f2bf2(fmaxf(acc[j][0] + bv0, 0.f), fmaxf(acc[j][1] + bv1, 0.f));
        u32 hi = f2bf2(fmaxf(acc[j][2] + bv0, 0.f), fmaxf(acc[j][3] + bv1, 0.f));
        Aw[(wrow + g) * ASTW + j * 4 + tc]     = lo;
        Aw[(wrow + g + 8) * ASTW + j * 4 + tc] = hi;
    }
    __syncthreads();
    for (int idx = tid; idx < 128 * 16; idx += 256) {
        int r = idx >> 4, q = idx & 15;
        if (row0 + r < NN)
            g_hbf[(size_t)(row0 + r) * 16 + q] = *(uint4*)(smc + SM_A + r * (AST * 2) + q * 16);
    }
}

// ---------------- K5: FUSED  Agg(h) + per-graph pool (16 rows / block) --------
__global__ void __launch_bounds__(256) agg_pool_kernel(const void* __restrict__ batch,
                                                       const void* __restrict__ ei) {
    __shared__ float rows[16][128];
    __shared__ int rowg[16];
    int tid = threadIdx.x;
    int wid = tid >> 5, lane = tid & 31;
    int sub = lane & 15, half = lane >> 4;
    int r = wid * 2 + half;                // 0..15
    int dst = blockIdx.x * 16 + r;
    int is64 = detect64(ei);
    const uint4* sfh = (const uint4*)g_hbf;

    if (dst < NN) {
        float4 o0, o1;
        agg_row2_bf(sfh, dst, sub, o0, o1);
        *(float4*)(&rows[r][sub * 8])     = o0;
        *(float4*)(&rows[r][sub * 8 + 4]) = o1;
        if (sub == 0) rowg[r] = load_idx(batch, dst, is64) & (GG - 1);
    } else if (sub == 0) {
        rowg[r] = -1;
    }
    __syncthreads();

    if (tid < 128) {
        int t = tid;
        int cur = rowg[0];
        float acc = 0.f;
        #pragma unroll
        for (int rr = 0; rr < 16; rr++) {
            int g = rowg[rr];
            if (g < 0) break;
            if (g != cur) {
                atomicAdd(&g_sums[cur * HH + t], acc);
                acc = 0.f; cur = g;
            }
            acc += rows[rr][t];
        }
        if (cur >= 0) atomicAdd(&g_sums[cur * HH + t], acc);
    } else if (tid == 128) {
        int cur = rowg[0];
        float c = 0.f;
        #pragma unroll
        for (int rr = 0; rr < 16; rr++) {
            int g = rowg[rr];
            if (g < 0) break;
            if (g != cur) { atomicAdd(&g_cnt[cur], c); c = 0.f; cur = g; }
            c += 1.f;
        }
        if (cur >= 0) atomicAdd(&g_cnt[cur], c);
    }
}

// ---------------- K6: per-graph head: z = p@W2+b2 ; logits = z@Wlin+blin ------
__global__ void __launch_bounds__(128) final_kernel(const float* __restrict__ W2,
                                                    const float* __restrict__ b2,
                                                    const float* __restrict__ Wlin,
                                                    const float* __restrict__ blin,
                                                    float* __restrict__ out) {
    __shared__ float p[HH];
    __shared__ float z[HH];
    int g = blockIdx.x;            // 0..63
    int t = threadIdx.x;           // 0..127
    float inv = 1.f / fmaxf(g_cnt[g], 1.f);
    p[t] = g_sums[g * HH + t] * inv;
    __syncthreads();
    float s = b2[t];
    #pragma unroll 8
    for (int k = 0; k < HH; k++) s = fmaf(p[k], W2[k * HH + t], s);
    z[t] = s;
    __syncthreads();
    if (t < CC) {
        float l = blin[t];
        #pragma unroll 8
        for (int j = 0; j < HH; j++) l = fmaf(z[j], Wlin[j * CC + t], l);
        out[g * CC + t] = l;
    }
}

// ---------------- host launch ----------------
extern "C" void kernel_launch(void* const* d_in, const int* in_sizes, int n_in,
                              void* d_out, int out_size) {
    const float* x    = (const float*)d_in[0];
    const float* W1   = (const float*)d_in[1];
    const float* b1   = (const float*)d_in[2];
    const float* W2   = (const float*)d_in[3];
    const float* b2   = (const float*)d_in[4];
    const float* Wlin = (const float*)d_in[5];
    const float* blin = (const float*)d_in[6];
    const void*  ei   = d_in[7];   // edge_index: int32 or int64, detected per block
    const void*  bt   = d_in[8];   // batch: same index dtype
    float* out = (float*)d_out;

    cudaFuncSetAttribute(fused_agg_mma, cudaFuncAttributeMaxDynamicSharedMemorySize, FUSED_SMEM);

    void* zp;
    cudaGetSymbolAddress(&zp, g_z);
    cudaMemsetAsync(zp, 0, sizeof(ZReg));                       // deg/bstat/sums/cnt

    prep_kernel<<<(NN * 16 + 255) / 256, 256>>>(x, ei, W1);     // x->bf16 + deg + W1 split
    scan_kernel<<<SCAN_NB, SCAN_T>>>();                         // single-pass lookback scan
    fill_kernel<<<(EE + 255) / 256, 256>>>(ei);

    // layer 1 fused: h = relu(Agg(x) @ W1 + b1)  (split-bf16 mma.sync)
    fused_agg_mma<<<(NN + 127) / 128, 256, FUSED_SMEM>>>(b1);

    // layer 2 folded + fused: pool(Agg(h)); then per-graph head
    agg_pool_kernel<<<(NN + 15) / 16, 256>>>(bt, ei);
    final_kernel<<<GG, 128>>>(W2, b2, Wlin, blin, out);
}

// round 17
// speedup vs baseline: 1.1680x; 1.1680x over previous
#include <cuda_runtime.h>
#include <cuda_bf16.h>
#include <cstdint>

// Problem constants (match reference)
#define NN 50000
#define EE 600000
#define GG 64
#define HH 128
#define CC 10

#define SCAN_T 256
#define SCAN_NB ((NN + SCAN_T - 1) / SCAN_T)   // 196

typedef unsigned long long u64;
typedef unsigned int u32;
typedef unsigned short u16;

// ---------------- scratch (static device globals; no runtime alloc) ----------------
// Zeroed-per-launch region: one contiguous memset.
struct ZReg {
    int   deg[NN];
    int   bstat[SCAN_NB];          // lookback status: 0=none,1=agg ready,2=prefix ready
    float sums[GG * HH];
    float cnt[GG];
};
__device__ ZReg g_z;
#define g_deg   g_z.deg
#define g_bstat g_z.bstat
#define g_sums  g_z.sums
#define g_cnt   g_z.cnt

__device__ int   g_off[NN];        // CSR offsets (fill bumps to end)
__device__ float g_dinv[NN];       // rsqrt(deg+1)
__device__ int   g_bagg[SCAN_NB];  // per-block degree totals (published)
__device__ int   g_bpre[SCAN_NB];  // inclusive prefixes (published)
__device__ int2  g_csr[EE];        // {src, bits(dinv[src])} grouped by dst
__device__ uint4 g_xbf[NN * 16];   // x in bf16 (row = 16 uint4 = 128 bf16)
__device__ uint4 g_hbf[NN * 16];   // h = relu(Agg(x)@W1+b1) in bf16
// Precomputed W1 split planes, pre-padded [n][136] bf16; hi plane then lo plane.
#define AST 136   // padded row stride in bf16
#define ASTW 68   // in 32-bit words
#define PLANE_U16 (128 * AST)              // 17408 u16 per plane
__device__ uint4 g_W1p[(PLANE_U16 * 2) / 8];   // 4352 uint4 = 69632 B

// ---------------- bf16 helpers ----------------
__device__ __forceinline__ float4 bf2f4(u32 a, u32 b) {
    __nv_bfloat162 p0 = *(__nv_bfloat162*)&a;
    __nv_bfloat162 p1 = *(__nv_bfloat162*)&b;
    float2 f0 = __bfloat1622float2(p0);
    float2 f1 = __bfloat1622float2(p1);
    return make_float4(f0.x, f0.y, f1.x, f1.y);
}
__device__ __forceinline__ u32 f2bf2(float a, float b) {
    __nv_bfloat162 p = __float22bfloat162_rn(make_float2(a, b));
    return *(u32*)&p;
}

// ---------------- warp-level bf16 MMA (sm_80+ PTX, legal on compute_103) -------
__device__ __forceinline__ void mma16816(float* d, u32 a0, u32 a1, u32 a2, u32 a3,
                                         u32 b0, u32 b1) {
    asm volatile(
        "mma.sync.aligned.m16n8k16.row.col.f32.bf16.bf16.f32 "
        "{%0,%1,%2,%3}, {%4,%5,%6,%7}, {%8,%9}, {%0,%1,%2,%3};"
        : "+f"(d[0]), "+f"(d[1]), "+f"(d[2]), "+f"(d[3])
        : "r"(a0), "r"(a1), "r"(a2), "r"(a3), "r"(b0), "r"(b1));
}

// ---------------- inline dtype detect (no kernel, no global flag) --------------
__device__ __forceinline__ int detect64(const void* ei) {
    const long long* p = (const long long*)ei;
    long long m = p[1] | p[3] | p[5] | p[7] | p[9] | p[11] | p[13] | p[15];
    return ((u64)m) < (1ULL << 32);
}

// ---------------- index load helper (dtype-agnostic) ----------------
__device__ __forceinline__ int load_idx(const void* p, long long i, int is64) {
    if (is64) return (int)(((const long long*)p)[i]);
    return ((const int*)p)[i];
}

// ---------------- K1: x->bf16, in-degrees, W1 split planes ----------------
__global__ void prep_kernel(const float* __restrict__ x, const void* __restrict__ ei,
                            const float* __restrict__ W1) {
    int i = blockIdx.x * blockDim.x + threadIdx.x;
    if (i < NN * 16) {
        float4 va = ((const float4*)x)[i * 2];
        float4 vb = ((const float4*)x)[i * 2 + 1];
        uint4 o;
        o.x = f2bf2(va.x, va.y);
        o.y = f2bf2(va.z, va.w);
        o.z = f2bf2(vb.x, vb.y);
        o.w = f2bf2(vb.z, vb.w);
        g_xbf[i] = o;
    }
    if (i < EE) {
        int is64 = detect64(ei);
        int dst = load_idx(ei, (long long)EE + i, is64);
        dst = min(max(dst, 0), NN - 1);
        atomicAdd(&g_deg[dst], 1);
    }
    if (i < 128 * 128) {
        int k = i >> 7, n = i & 127;
        float w = W1[i];
        __nv_bfloat16 hi = __float2bfloat16_rn(w);
        __nv_bfloat16 lo = __float2bfloat16_rn(w - __bfloat162float(hi));
        u16* planes = (u16*)g_W1p;
        planes[n * AST + k]             = *(u16*)&hi;
        planes[PLANE_U16 + n * AST + k] = *(u16*)&lo;
    }
}

// ---------------- K2: single-pass scan, WARP-PARALLEL lookback ----------------
__global__ void __launch_bounds__(SCAN_T) scan_kernel() {
    __shared__ int ws[8];
    __shared__ int sh_base;
    int b = blockIdx.x, t = threadIdx.x;
    int i = b * SCAN_T + t;
    int v = (i < NN) ? g_deg[i] : 0;
    if (i < NN) g_dinv[i] = rsqrtf((float)(v + 1));

    // block-local inclusive scan (shfl)
    int lane = t & 31, w = t >> 5;
    int s = v;
    #pragma unroll
    for (int o = 1; o < 32; o <<= 1) {
        int u = __shfl_up_sync(0xffffffffu, s, o);
        if (lane >= o) s += u;
    }
    if (lane == 31) ws[w] = s;
    __syncthreads();
    if (w == 0 && lane < 8) {
        int x2 = ws[lane];
        #pragma unroll
        for (int o = 1; o < 8; o <<= 1) {
            int u = __shfl_up_sync(0xffu, x2, o, 8);
            if (lane >= o) x2 += u;
        }
        ws[lane] = x2;
    }
    __syncthreads();
    if (w > 0) s += ws[w - 1];                  // inclusive within block

    // publish aggregate
    if (t == SCAN_T - 1) {
        if (b == 0) {
            atomicExch(&g_bpre[0], s);
            __threadfence();
            atomicExch(&g_bstat[0], 2);
        } else {
            atomicExch(&g_bagg[b], s);
            __threadfence();
            atomicExch(&g_bstat[b], 1);
        }
    }

    // warp-parallel lookback (warp 0): 32 predecessors per round
    if (w == 0) {
        int base = 0;
        if (b > 0) {
            int j = b - 1;
            bool done = false;
            while (!done) {
                int idx = j - lane;             // lane 0 = nearest predecessor
                int st = 0, val = 0;
                if (idx >= 0) {
                    do { st = atomicAdd(&g_bstat[idx], 0); } while (st == 0);
                    __threadfence();
                    val = (st == 2) ? atomicAdd(&g_bpre[idx], 0)
                                    : atomicAdd(&g_bagg[idx], 0);
                }
                unsigned pmask = __ballot_sync(0xffffffffu, idx >= 0 && st == 2);
                int contrib;
                if (pmask) {
                    int firstp = __ffs(pmask) - 1;   // nearest block with full prefix
                    contrib = (lane <= firstp) ? val : 0;
                    done = true;
                } else {
                    contrib = (idx >= 0) ? val : 0;
                    j -= 32;
                    if (j < 0) done = true;
                }
                #pragma unroll
                for (int o = 16; o > 0; o >>= 1)
                    contrib += __shfl_down_sync(0xffffffffu, contrib, o);
                base += __shfl_sync(0xffffffffu, contrib, 0);
            }
        }
        if (lane == 0) sh_base = base;
    }
    __syncthreads();
    int base = sh_base;

    // publish inclusive prefix for successors
    if (t == SCAN_T - 1 && b > 0) {
        atomicExch(&g_bpre[b], base + s);
        __threadfence();
        atomicExch(&g_bstat[b], 2);
    }

    if (i < NN) g_off[i] = base + s - v;        // exclusive offset
}

// ---------------- K3: scatter edges into dst-grouped CSR (bumps g_off) --------
__global__ void fill_kernel(const void* __restrict__ ei) {
    int e = blockIdx.x * blockDim.x + threadIdx.x;
    if (e < EE) {
        int is64 = detect64(ei);
        int src = load_idx(ei, e, is64);
        int dst = load_idx(ei, (long long)EE + e, is64);
        src = min(max(src, 0), NN - 1);
        dst = min(max(dst, 0), NN - 1);
        int pos = atomicAdd(&g_off[dst], 1);    // g_off[dst] ends at CSR end
        g_csr[pos] = make_int2(src, __float_as_int(g_dinv[src]));
    }
}

// ---------------- dual-row agg (predicated batch-4, no serial tail) -----------
// NOTE: after fill, g_off[dst] == END of dst's edge range; start = end - deg.
__device__ __forceinline__ void fma4(float4& a, float w, const float4& v) {
    a.x = fmaf(w, v.x, a.x); a.y = fmaf(w, v.y, a.y);
    a.z = fmaf(w, v.z, a.z); a.w = fmaf(w, v.w, a.w);
}

__device__ __forceinline__ void agg_row2_bf(const uint4* __restrict__ sf, int dst, int sub,
                                            float4& o0, float4& o1) {
    float di = g_dinv[dst];
    uint4 sv = sf[dst * 16 + sub];                 // self loop
    float4 a0 = bf2f4(sv.x, sv.y);
    float4 a1 = bf2f4(sv.z, sv.w);
    a0.x *= di; a0.y *= di; a0.z *= di; a0.w *= di;
    a1.x *= di; a1.y *= di; a1.z *= di; a1.w *= di;
    float4 b0 = make_float4(0.f, 0.f, 0.f, 0.f);
    float4 b1 = make_float4(0.f, 0.f, 0.f, 0.f);

    int end = g_off[dst];
    int e0 = end - g_deg[dst];
    int last = end - 1;
    for (int b = e0; b < end; b += 4) {
        int i1 = b + 1, i2 = b + 2, i3 = b + 3;
        int2 c0 = g_csr[b];
        int2 c1 = g_csr[min(i1, last)];
        int2 c2 = g_csr[min(i2, last)];
        int2 c3 = g_csr[min(i3, last)];
        uint4 v0 = sf[c0.x * 16 + sub];
        uint4 v1 = sf[c1.x * 16 + sub];
        uint4 v2 = sf[c2.x * 16 + sub];
        uint4 v3 = sf[c3.x * 16 + sub];
        float w0 = __int_as_float(c0.y);
        float w1 = (i1 < end) ? __int_as_float(c1.y) : 0.f;
        float w2 = (i2 < end) ? __int_as_float(c2.y) : 0.f;
        float w3 = (i3 < end) ? __int_as_float(c3.y) : 0.f;
        fma4(a0, w0, bf2f4(v0.x, v0.y)); fma4(a1, w0, bf2f4(v0.z, v0.w));
        fma4(b0, w1, bf2f4(v1.x, v1.y)); fma4(b1, w1, bf2f4(v1.z, v1.w));
        fma4(a0, w2, bf2f4(v2.x, v2.y)); fma4(a1, w2, bf2f4(v2.z, v2.w));
        fma4(b0, w3, bf2f4(v3.x, v3.y)); fma4(b1, w3, bf2f4(v3.z, v3.w));
    }
    a0.x += b0.x; a0.y += b0.y; a0.z += b0.z; a0.w += b0.w;
    a1.x += b1.x; a1.y += b1.y; a1.z += b1.z; a1.w += b1.w;
    a0.x *= di; a0.y *= di; a0.z *= di; a0.w *= di;
    a1.x *= di; a1.y *= di; a1.z *= di; a1.w *= di;
    o0 = a0; o1 = a1;
}

// ---------------- K4: FUSED  h = relu(Agg(x) @ W1 + b1) via split-bf16 MMA ----
#define SM_BIAS 512
#define SM_A 1024
#define SM_BHI (1024 + 34816)
#define SM_BLO (1024 + 34816 + 34816)
#define FUSED_SMEM (1024 + 34816 + 34816 + 34816)

__global__ void __launch_bounds__(256, 2)
fused_agg_mma(const float* __restrict__ b1) {
    extern __shared__ char smc[];
    float* bias_s = (float*)(smc + SM_BIAS);
    u32* Aw  = (u32*)(smc + SM_A);
    u32* BwH = (u32*)(smc + SM_BHI);
    u32* BwL = (u32*)(smc + SM_BLO);
    int tid = threadIdx.x;
    int wid = tid >> 5, lane = tid & 31;
    int sub = lane & 15, half = lane >> 4;
    int row0 = blockIdx.x * 128;

    if (tid < 128) bias_s[tid] = b1[tid];

    // ---- B planes: straight uint4 copy of precomputed Whi/Wlo ----
    uint4* bdst = (uint4*)(smc + SM_BHI);
    #pragma unroll 4
    for (int i = tid; i < (PLANE_U16 * 2) / 8; i += 256)
        bdst[i] = g_W1p[i];

    // ---- A tile: aggregate 128 rows into As[m][k] bf16 (stride 136) ----
    const uint4* sfx = (const uint4*)g_xbf;
    #pragma unroll 1
    for (int r = 0; r < 8; r++) {
        int m = wid * 16 + r * 2 + half;
        int dst = row0 + m;
        float4 o0 = make_float4(0.f, 0.f, 0.f, 0.f);
        float4 o1 = make_float4(0.f, 0.f, 0.f, 0.f);
        if (dst < NN) agg_row2_bf(sfx, dst, sub, o0, o1);
        uint4 pk;
        pk.x = f2bf2(o0.x, o0.y); pk.y = f2bf2(o0.z, o0.w);
        pk.z = f2bf2(o1.x, o1.y); pk.w = f2bf2(o1.z, o1.w);
        *(uint4*)(smc + SM_A + m * (AST * 2) + sub * 16) = pk;
    }
    __syncthreads();

    // ---- MMA: each warp computes rows [wid*16, +16) x all 128 cols ----
    int g = lane >> 2, tc = lane & 3;
    int wrow = wid * 16;
    float acc[16][4];
    #pragma unroll
    for (int j = 0; j < 16; j++)
        #pragma unroll
        for (int q = 0; q < 4; q++) acc[j][q] = 0.f;

    #pragma unroll 1
    for (int ks = 0; ks < 8; ks++) {
        int k0w = ks * 8;                       // 16 bf16 = 8 words
        u32 a0 = Aw[(wrow + g) * ASTW + k0w + tc];
        u32 a1 = Aw[(wrow + g + 8) * ASTW + k0w + tc];
        u32 a2 = Aw[(wrow + g) * ASTW + k0w + tc + 4];
        u32 a3 = Aw[(wrow + g + 8) * ASTW + k0w + tc + 4];
        #pragma unroll
        for (int j = 0; j < 16; j++) {
            int bi = (j * 8 + g) * ASTW + k0w + tc;
            u32 bh0 = BwH[bi], bh1 = BwH[bi + 4];
            u32 bl0 = BwL[bi], bl1 = BwL[bi + 4];
            mma16816(acc[j], a0, a1, a2, a3, bh0, bh1);
            mma16816(acc[j], a0, a1, a2, a3, bl0, bl1);
        }
    }
    __syncthreads();     // done reading As/Bs; reuse As for output staging

    // ---- epilogue: bias + relu, pack bf16 into As, then coalesced store ----
    #pragma unroll
    for (int j = 0; j < 16; j++) {
        int c = j * 8 + tc * 2;
        float bv0 = bias_s[c], bv1 = bias_s[c + 1];
        u32 lo = f2bf2(fmaxf(acc[j][0] + bv0, 0.f), fmaxf(acc[j][1] + bv1, 0.f));
        u32 hi = f2bf2(fmaxf(acc[j][2] + bv0, 0.f), fmaxf(acc[j][3] + bv1, 0.f));
        Aw[(wrow + g) * ASTW + j * 4 + tc]     = lo;
        Aw[(wrow + g + 8) * ASTW + j * 4 + tc] = hi;
    }
    __syncthreads();
    for (int idx = tid; idx < 128 * 16; idx += 256) {
        int r = idx >> 4, q = idx & 15;
        if (row0 + r < NN)
            g_hbf[(size_t)(row0 + r) * 16 + q] = *(uint4*)(smc + SM_A + r * (AST * 2) + q * 16);
    }
}

// ---------------- K5: FUSED  Agg(h) + per-graph pool (16 rows / block) --------
__global__ void __launch_bounds__(256) agg_pool_kernel(const void* __restrict__ batch,
                                                       const void* __restrict__ ei) {
    __shared__ float rows[16][128];
    __shared__ int rowg[16];
    int tid = threadIdx.x;
    int wid = tid >> 5, lane = tid & 31;
    int sub = lane & 15, half = lane >> 4;
    int r = wid * 2 + half;                // 0..15
    int dst = blockIdx.x * 16 + r;
    int is64 = detect64(ei);
    const uint4* sfh = (const uint4*)g_hbf;

    if (dst < NN) {
        float4 o0, o1;
        agg_row2_bf(sfh, dst, sub, o0, o1);
        *(float4*)(&rows[r][sub * 8])     = o0;
        *(float4*)(&rows[r][sub * 8 + 4]) = o1;
        if (sub == 0) rowg[r] = load_idx(batch, dst, is64) & (GG - 1);
    } else if (sub == 0) {
        rowg[r] = -1;
    }
    __syncthreads();

    if (tid < 128) {
        int t = tid;
        int cur = rowg[0];
        float acc = 0.f;
        #pragma unroll
        for (int rr = 0; rr < 16; rr++) {
            int g = rowg[rr];
            if (g < 0) break;
            if (g != cur) {
                atomicAdd(&g_sums[cur * HH + t], acc);
                acc = 0.f; cur = g;
            }
            acc += rows[rr][t];
        }
        if (cur >= 0) atomicAdd(&g_sums[cur * HH + t], acc);
    } else if (tid == 128) {
        int cur = rowg[0];
        float c = 0.f;
        #pragma unroll
        for (int rr = 0; rr < 16; rr++) {
            int g = rowg[rr];
            if (g < 0) break;
            if (g != cur) { atomicAdd(&g_cnt[cur], c); c = 0.f; cur = g; }
            c += 1.f;
        }
        if (cur >= 0) atomicAdd(&g_cnt[cur], c);
    }
}

// ---------------- K6: per-graph head: z = p@W2+b2 ; logits = z@Wlin+blin ------
__global__ void __launch_bounds__(128) final_kernel(const float* __restrict__ W2,
                                                    const float* __restrict__ b2,
                                                    const float* __restrict__ Wlin,
                                                    const float* __restrict__ blin,
                                                    float* __restrict__ out) {
    __shared__ float p[HH];
    __shared__ float z[HH];
    int g = blockIdx.x;            // 0..63
    int t = threadIdx.x;           // 0..127
    float inv = 1.f / fmaxf(g_cnt[g], 1.f);
    p[t] = g_sums[g * HH + t] * inv;
    __syncthreads();
    float s = b2[t];
    #pragma unroll 8
    for (int k = 0; k < HH; k++) s = fmaf(p[k], W2[k * HH + t], s);
    z[t] = s;
    __syncthreads();
    if (t < CC) {
        float l = blin[t];
        #pragma unroll 8
        for (int j = 0; j < HH; j++) l = fmaf(z[j], Wlin[j * CC + t], l);
        out[g * CC + t] = l;
    }
}

// ---------------- host launch ----------------
extern "C" void kernel_launch(void* const* d_in, const int* in_sizes, int n_in,
                              void* d_out, int out_size) {
    const float* x    = (const float*)d_in[0];
    const float* W1   = (const float*)d_in[1];
    const float* b1   = (const float*)d_in[2];
    const float* W2   = (const float*)d_in[3];
    const float* b2   = (const float*)d_in[4];
    const float* Wlin = (const float*)d_in[5];
    const float* blin = (const float*)d_in[6];
    const void*  ei   = d_in[7];   // edge_index: int32 or int64, detected per block
    const void*  bt   = d_in[8];   // batch: same index dtype
    float* out = (float*)d_out;

    cudaFuncSetAttribute(fused_agg_mma, cudaFuncAttributeMaxDynamicSharedMemorySize, FUSED_SMEM);

    void* zp;
    cudaGetSymbolAddress(&zp, g_z);
    cudaMemsetAsync(zp, 0, sizeof(ZReg));                       // deg/bstat/sums/cnt

    prep_kernel<<<(NN * 16 + 255) / 256, 256>>>(x, ei, W1);     // x->bf16 + deg + W1 split
    scan_kernel<<<SCAN_NB, SCAN_T>>>();                         // warp-parallel lookback scan
    fill_kernel<<<(EE + 255) / 256, 256>>>(ei);

    // layer 1 fused: h = relu(Agg(x) @ W1 + b1)  (split-bf16 mma.sync)
    fused_agg_mma<<<(NN + 127) / 128, 256, FUSED_SMEM>>>(b1);

    // layer 2 folded + fused: pool(Agg(h)); then per-graph head
    agg_pool_kernel<<<(NN + 15) / 16, 256>>>(bt, ei);
    final_kernel<<<GG, 128>>>(W2, b2, Wlin, blin, out);
}